// round 2
// baseline (speedup 1.0000x reference)
#include <cuda_runtime.h>
#include <cstddef>

// Problem constants
#define B_    4
#define N_    4096
#define M_    1024
#define QD_   1024
#define CD_   768
#define H_    16
#define D_    64
#define INNER 1024

// Scratch (static device allocations are allowed)
__device__ float g_Q [B_ * N_ * INNER];   // 64 MB
__device__ float g_K [B_ * M_ * INNER];   // 16 MB
__device__ float g_V [B_ * M_ * INNER];   // 16 MB
__device__ float g_AO[B_ * N_ * INNER];   // 64 MB

// ---------------------------------------------------------------------------
// SGEMM: C[M,N] = A[M,K] @ B[K,N] (+ bias), row-major, all dims multiples of
// tile sizes (M: 128, N: 128, K: 16). 256 threads, 8x8 per-thread tile with
// split fragments (cols {tx*4, 64+tx*4}) for conflict-free LDS.128.
// ---------------------------------------------------------------------------
template <int BM, int BN, int BK>
__global__ __launch_bounds__(256) void sgemm_kernel(
    const float* __restrict__ A, const float* __restrict__ B,
    float* __restrict__ C, int M, int N, int K, const float* __restrict__ bias)
{
    __shared__ float As[BK][BM];
    __shared__ float Bs[BK][BN];

    const int tid  = threadIdx.x;
    const int brow = blockIdx.y * BM;
    const int bcol = blockIdx.x * BN;
    const int ty   = tid >> 4;     // 0..15
    const int tx   = tid & 15;     // 0..15

    float acc[8][8];
    #pragma unroll
    for (int i = 0; i < 8; ++i)
        #pragma unroll
        for (int j = 0; j < 8; ++j) acc[i][j] = 0.f;

    const float* Ab = A + (size_t)brow * K;
    const float* Bb = B + bcol;

    for (int k0 = 0; k0 < K; k0 += BK) {
        // Load A tile (BM x BK = 2048 floats), store transposed As[k][m]
        #pragma unroll
        for (int i = 0; i < (BM * BK) / (256 * 4); ++i) {
            int idx = (tid + i * 256) * 4;
            int r = idx / BK, c = idx % BK;
            float4 v = *reinterpret_cast<const float4*>(Ab + (size_t)r * K + k0 + c);
            As[c + 0][r] = v.x; As[c + 1][r] = v.y;
            As[c + 2][r] = v.z; As[c + 3][r] = v.w;
        }
        // Load B tile (BK x BN = 2048 floats)
        #pragma unroll
        for (int i = 0; i < (BK * BN) / (256 * 4); ++i) {
            int idx = (tid + i * 256) * 4;
            int r = idx / BN, c = idx % BN;
            *reinterpret_cast<float4*>(&Bs[r][c]) =
                *reinterpret_cast<const float4*>(Bb + (size_t)(k0 + r) * N + c);
        }
        __syncthreads();

        #pragma unroll
        for (int kk = 0; kk < BK; ++kk) {
            float4 a0 = *reinterpret_cast<const float4*>(&As[kk][ty * 4]);
            float4 a1 = *reinterpret_cast<const float4*>(&As[kk][64 + ty * 4]);
            float4 b0 = *reinterpret_cast<const float4*>(&Bs[kk][tx * 4]);
            float4 b1 = *reinterpret_cast<const float4*>(&Bs[kk][64 + tx * 4]);
            const float ar[8] = {a0.x, a0.y, a0.z, a0.w, a1.x, a1.y, a1.z, a1.w};
            const float br[8] = {b0.x, b0.y, b0.z, b0.w, b1.x, b1.y, b1.z, b1.w};
            #pragma unroll
            for (int i = 0; i < 8; ++i)
                #pragma unroll
                for (int j = 0; j < 8; ++j)
                    acc[i][j] = fmaf(ar[i], br[j], acc[i][j]);
        }
        __syncthreads();
    }

    // Epilogue: rows {brow+ty*4+i, brow+64+ty*4+i}, cols {bcol+tx*4, bcol+64+tx*4}
    #pragma unroll
    for (int i = 0; i < 8; ++i) {
        int r = brow + ((i < 4) ? (ty * 4 + i) : (64 + ty * 4 + i - 4));
        #pragma unroll
        for (int half = 0; half < 2; ++half) {
            int c = bcol + half * 64 + tx * 4;
            float4 v;
            v.x = acc[i][half * 4 + 0];
            v.y = acc[i][half * 4 + 1];
            v.z = acc[i][half * 4 + 2];
            v.w = acc[i][half * 4 + 3];
            if (bias) {
                v.x += bias[c + 0]; v.y += bias[c + 1];
                v.z += bias[c + 2]; v.w += bias[c + 3];
            }
            *reinterpret_cast<float4*>(C + (size_t)r * N + c) = v;
        }
    }
}

// ---------------------------------------------------------------------------
// Flash attention (fp32): one query row per thread, 128 rows per CTA.
// K/V tiles of 32 rows staged in smem; per-thread scores spilled to smem
// (Ssm[j][t], conflict-free) to keep register pressure manageable.
// ---------------------------------------------------------------------------
#define KB 32

__global__ __launch_bounds__(128) void attn_kernel(
    const float* __restrict__ Q, const float* __restrict__ K,
    const float* __restrict__ V, float* __restrict__ O)
{
    __shared__ float Ks[KB][D_];
    __shared__ float Vs[KB][D_];
    __shared__ float Ssm[KB][128];

    const int t = threadIdx.x;
    const int b = blockIdx.z;
    const int h = blockIdx.y;
    const int n = blockIdx.x * 128 + t;
    const float scale = 0.125f;  // 64^-0.5

    // Load this thread's query row, pre-scaled
    const float* qp = Q + ((size_t)(b * N_ + n) * INNER) + h * D_;
    float q[D_];
    #pragma unroll
    for (int d = 0; d < D_; d += 4) {
        float4 v = *reinterpret_cast<const float4*>(qp + d);
        q[d] = v.x * scale; q[d + 1] = v.y * scale;
        q[d + 2] = v.z * scale; q[d + 3] = v.w * scale;
    }

    float o[D_];
    #pragma unroll
    for (int d = 0; d < D_; ++d) o[d] = 0.f;
    float mrun = -1e30f, lrun = 0.f;

    for (int kb = 0; kb < M_; kb += KB) {
        __syncthreads();  // previous tile fully consumed
        // Cooperative load of K/V tile: KB*D_ = 2048 floats = 512 float4 each
        #pragma unroll
        for (int i = 0; i < (KB * D_) / (128 * 4); ++i) {
            int idx = t + i * 128;               // float4 slot 0..511
            int j = idx >> 4;                    // 0..KB-1
            int dv = (idx & 15) * 4;             // 0..60
            size_t g = ((size_t)(b * M_ + kb + j) * INNER) + h * D_ + dv;
            *reinterpret_cast<float4*>(&Ks[j][dv]) = *reinterpret_cast<const float4*>(K + g);
            *reinterpret_cast<float4*>(&Vs[j][dv]) = *reinterpret_cast<const float4*>(V + g);
        }
        __syncthreads();

        // Pass 1: scores + block max
        float bm = -1e30f;
        #pragma unroll 8
        for (int j = 0; j < KB; ++j) {
            float acc = 0.f;
            #pragma unroll
            for (int d = 0; d < D_; d += 4) {
                float4 kv = *reinterpret_cast<const float4*>(&Ks[j][d]);
                acc += q[d] * kv.x + q[d + 1] * kv.y + q[d + 2] * kv.z + q[d + 3] * kv.w;
            }
            Ssm[j][t] = acc;
            bm = fmaxf(bm, acc);
        }

        float mnew  = fmaxf(mrun, bm);
        float alpha = __expf(mrun - mnew);
        lrun *= alpha;
        #pragma unroll
        for (int d = 0; d < D_; ++d) o[d] *= alpha;
        mrun = mnew;

        // Pass 2: exp + AV accumulate
        #pragma unroll 4
        for (int j = 0; j < KB; ++j) {
            float p = __expf(Ssm[j][t] - mnew);
            lrun += p;
            #pragma unroll
            for (int d = 0; d < D_; d += 4) {
                float4 vv = *reinterpret_cast<const float4*>(&Vs[j][d]);
                o[d]     += p * vv.x; o[d + 1] += p * vv.y;
                o[d + 2] += p * vv.z; o[d + 3] += p * vv.w;
            }
        }
    }

    float inv = 1.f / lrun;
    float* op = O + ((size_t)(b * N_ + n) * INNER) + h * D_;
    #pragma unroll
    for (int d = 0; d < D_; d += 4) {
        float4 v;
        v.x = o[d] * inv; v.y = o[d + 1] * inv;
        v.z = o[d + 2] * inv; v.w = o[d + 3] * inv;
        *reinterpret_cast<float4*>(op + d) = v;
    }
}

// ---------------------------------------------------------------------------
// Launch
// ---------------------------------------------------------------------------
extern "C" void kernel_launch(void* const* d_in, const int* in_sizes, int n_in,
                              void* d_out, int out_size)
{
    const float* x   = (const float*)d_in[0];  // [4,4096,1024]
    const float* ctx = (const float*)d_in[1];  // [4,1024,768]
    const float* Wq  = (const float*)d_in[2];  // [1024,1024]
    const float* Wk  = (const float*)d_in[3];  // [768,1024]
    const float* Wv  = (const float*)d_in[4];  // [768,1024]
    const float* Wo  = (const float*)d_in[5];  // [1024,1024]
    const float* bo  = (const float*)d_in[6];  // [1024]
    float* out = (float*)d_out;

    float *Qb, *Kb, *Vb, *AOb;
    cudaGetSymbolAddress((void**)&Qb,  g_Q);
    cudaGetSymbolAddress((void**)&Kb,  g_K);
    cudaGetSymbolAddress((void**)&Vb,  g_V);
    cudaGetSymbolAddress((void**)&AOb, g_AO);

    // Q = x @ Wq : [16384,1024] x [1024,1024]
    sgemm_kernel<128, 128, 16><<<dim3(INNER / 128, (B_ * N_) / 128), 256>>>(
        x, Wq, Qb, B_ * N_, INNER, QD_, nullptr);
    // K = ctx @ Wk : [4096,768] x [768,1024]
    sgemm_kernel<128, 128, 16><<<dim3(INNER / 128, (B_ * M_) / 128), 256>>>(
        ctx, Wk, Kb, B_ * M_, INNER, CD_, nullptr);
    // V = ctx @ Wv
    sgemm_kernel<128, 128, 16><<<dim3(INNER / 128, (B_ * M_) / 128), 256>>>(
        ctx, Wv, Vb, B_ * M_, INNER, CD_, nullptr);
    // Attention
    attn_kernel<<<dim3(N_ / 128, H_, B_), 128>>>(Qb, Kb, Vb, AOb);
    // out = AO @ Wo + bo
    sgemm_kernel<128, 128, 16><<<dim3(QD_ / 128, (B_ * N_) / 128), 256>>>(
        AOb, Wo, out, B_ * N_, QD_, INNER, bo);
}

// round 4
// speedup vs baseline: 1.3213x; 1.3213x over previous
#include <cuda_runtime.h>
#include <cuda_bf16.h>
#include <cstdint>
#include <cstddef>

// Problem constants
#define B_    4
#define N_    4096
#define M_    1024
#define QD_   1024
#define CD_   768
#define H_    16
#define D_    64
#define INNER 1024
#define BNQ   (B_ * N_)   // 16384 query rows
#define BMC   (B_ * M_)   // 4096 context rows

// ---------------------------------------------------------------------------
// Static device scratch
// ---------------------------------------------------------------------------
__device__ float g_Q[BNQ * INNER];
__device__ float g_K[BMC * INNER];
__device__ float g_V[BMC * INNER];

__device__ __nv_bfloat16 g_xhi[BNQ * QD_],  g_xlo[BNQ * QD_];
__device__ __nv_bfloat16 g_chi[BMC * CD_],  g_clo[BMC * CD_];
__device__ __nv_bfloat16 g_WqThi[INNER * QD_], g_WqTlo[INNER * QD_];
__device__ __nv_bfloat16 g_WkThi[INNER * CD_], g_WkTlo[INNER * CD_];
__device__ __nv_bfloat16 g_WvThi[INNER * CD_], g_WvTlo[INNER * CD_];
__device__ __nv_bfloat16 g_WoThi[QD_ * INNER], g_WoTlo[QD_ * INNER];
__device__ __nv_bfloat16 g_AOhi[BNQ * INNER], g_AOlo[BNQ * INNER];

// ---------------------------------------------------------------------------
// PTX helpers (base sm_80/sm_90 features only — no 'a'-gated instructions)
// ---------------------------------------------------------------------------
__device__ __forceinline__ uint32_t smem_u32(const void* p) {
    uint32_t a;
    asm("{ .reg .u64 t; cvta.to.shared.u64 t, %1; cvt.u32.u64 %0, t; }"
        : "=r"(a) : "l"(p));
    return a;
}

__device__ __forceinline__ void cp_async16(uint32_t dst, const void* src) {
    asm volatile("cp.async.cg.shared.global [%0], [%1], 16;"
                 :: "r"(dst), "l"(src) : "memory");
}

__device__ __forceinline__ void ldmatrix_x4(uint32_t& r0, uint32_t& r1,
                                            uint32_t& r2, uint32_t& r3, uint32_t a) {
    asm volatile("ldmatrix.sync.aligned.m8n8.x4.shared.b16 {%0,%1,%2,%3}, [%4];"
                 : "=r"(r0), "=r"(r1), "=r"(r2), "=r"(r3) : "r"(a));
}

__device__ __forceinline__ void mma16816(float* d, const uint32_t* a,
                                         const uint32_t* b) {
    asm volatile(
        "mma.sync.aligned.m16n8k16.row.col.f32.bf16.bf16.f32 "
        "{%0,%1,%2,%3}, {%4,%5,%6,%7}, {%8,%9}, {%0,%1,%2,%3};"
        : "+f"(d[0]), "+f"(d[1]), "+f"(d[2]), "+f"(d[3])
        : "r"(a[0]), "r"(a[1]), "r"(a[2]), "r"(a[3]), "r"(b[0]), "r"(b[1]));
}

// ---------------------------------------------------------------------------
// Conversion kernels: fp32 -> (hi, lo) bf16 split
// ---------------------------------------------------------------------------
__global__ void cvt_hilo_kernel(const float* __restrict__ in,
                                __nv_bfloat16* __restrict__ hi,
                                __nv_bfloat16* __restrict__ lo, int n4)
{
    int i = blockIdx.x * blockDim.x + threadIdx.x;
    if (i >= n4) return;
    float4 v = reinterpret_cast<const float4*>(in)[i];
    float f[4] = {v.x, v.y, v.z, v.w};
    __nv_bfloat16 h[4], l[4];
    #pragma unroll
    for (int j = 0; j < 4; ++j) {
        h[j] = __float2bfloat16(f[j]);
        l[j] = __float2bfloat16(f[j] - __bfloat162float(h[j]));
    }
    reinterpret_cast<__nv_bfloat162*>(hi)[i * 2 + 0] = __halves2bfloat162(h[0], h[1]);
    reinterpret_cast<__nv_bfloat162*>(hi)[i * 2 + 1] = __halves2bfloat162(h[2], h[3]);
    reinterpret_cast<__nv_bfloat162*>(lo)[i * 2 + 0] = __halves2bfloat162(l[0], l[1]);
    reinterpret_cast<__nv_bfloat162*>(lo)[i * 2 + 1] = __halves2bfloat162(l[2], l[3]);
}

// W [K,N] row-major  ->  T [N,K] (hi, lo) bf16
__global__ void transpose_cvt_kernel(const float* __restrict__ W,
                                     __nv_bfloat16* __restrict__ Thi,
                                     __nv_bfloat16* __restrict__ Tlo, int K, int N)
{
    __shared__ float t[32][33];
    int tx = threadIdx.x, ty = threadIdx.y;          // 32 x 8
    int n0 = blockIdx.x * 32, k0 = blockIdx.y * 32;
    #pragma unroll
    for (int j = 0; j < 4; ++j)
        t[ty + j * 8][tx] = W[(size_t)(k0 + ty + j * 8) * N + n0 + tx];
    __syncthreads();
    #pragma unroll
    for (int j = 0; j < 4; ++j) {
        float v = t[tx][ty + j * 8];
        int n = n0 + ty + j * 8, k = k0 + tx;
        __nv_bfloat16 h = __float2bfloat16(v);
        Thi[(size_t)n * K + k] = h;
        Tlo[(size_t)n * K + k] = __float2bfloat16(v - __bfloat162float(h));
    }
}

// ---------------------------------------------------------------------------
// mma.sync GEMM: C[M,N] = A[M,K] @ B^T, B stored [N,K] K-major.
// Split-bf16: C = Ahi*Bhi + Ahi*Blo + Alo*Bhi (fp32 accum).
// 256 threads, tile 128x128, BK=64, cp.async double-buffered.
// smem row stride 72 bf16 (144 B) -> conflict-free ldmatrix/STS.
// ---------------------------------------------------------------------------
#define SA_        72                       // smem row stride (bf16 elems)
#define TILE_B     (128 * SA_ * 2)          // 18432 bytes per tile
#define OFF_AHI    0
#define OFF_ALO    (TILE_B)
#define OFF_BHI    (2 * TILE_B)
#define OFF_BLO    (3 * TILE_B)
#define BUF_B      (4 * TILE_B)             // 73728 per buffer
#define GEMM_SMEM  (2 * BUF_B)              // 147456

__global__ __launch_bounds__(256) void mma_gemm_kernel(
    const __nv_bfloat16* __restrict__ Ahi, const __nv_bfloat16* __restrict__ Alo,
    const __nv_bfloat16* __restrict__ Bhi, const __nv_bfloat16* __restrict__ Blo,
    float* __restrict__ C, int Ndim, int Kdim, const float* __restrict__ bias)
{
    extern __shared__ __align__(128) char smem[];
    const uint32_t sb = smem_u32(smem);
    const int tid = threadIdx.x, wid = tid >> 5, l = tid & 31;
    const int warp_m = wid >> 2, warp_n = wid & 3;
    const int brow = blockIdx.y * 128, bcol = blockIdx.x * 128;

    // ldmatrix per-lane base coordinates
    const int a_row = warp_m * 64 + (l & 7) + ((l >> 3) & 1) * 8;   // + im*16
    const int a_col = ((l >> 4) & 1) * 8;                           // + ks*16
    const int b_row = warp_n * 32 + (l & 7) + ((l >> 4) & 1) * 8;   // + in16*16
    const int b_col = ((l >> 3) & 1) * 8;                           // + ks*16
    const uint32_t aOff = (uint32_t)(a_row * SA_ + a_col) * 2;
    const uint32_t bOff = (uint32_t)(b_row * SA_ + b_col) * 2;

    float acc[4][4][4];
    #pragma unroll
    for (int im = 0; im < 4; ++im)
        #pragma unroll
        for (int j = 0; j < 4; ++j)
            #pragma unroll
            for (int q = 0; q < 4; ++q) acc[im][j][q] = 0.f;

    const int nch = Kdim >> 6;

    // stage chunk ch into buffer bb
    auto stage = [&](int ch, int bb) {
        const int k0 = ch << 6;
        const uint32_t base = sb + bb * BUF_B;
        #pragma unroll
        for (int i = 0; i < 4; ++i) {
            int s = tid + i * 256;         // 0..1023
            int r = s >> 3, c = s & 7;
            uint32_t so = (uint32_t)(r * 144 + c * 16);
            size_t ga = (size_t)(brow + r) * Kdim + k0 + c * 8;
            size_t gb = (size_t)(bcol + r) * Kdim + k0 + c * 8;
            cp_async16(base + OFF_AHI + so, Ahi + ga);
            cp_async16(base + OFF_ALO + so, Alo + ga);
            cp_async16(base + OFF_BHI + so, Bhi + gb);
            cp_async16(base + OFF_BLO + so, Blo + gb);
        }
        asm volatile("cp.async.commit_group;" ::: "memory");
    };

    stage(0, 0);

    for (int ch = 0; ch < nch; ++ch) {
        const int bb = ch & 1;
        if (ch + 1 < nch) {
            stage(ch + 1, bb ^ 1);
            asm volatile("cp.async.wait_group 1;" ::: "memory");
        } else {
            asm volatile("cp.async.wait_group 0;" ::: "memory");
        }
        __syncthreads();

        const uint32_t base = sb + bb * BUF_B;
        #pragma unroll
        for (int ks = 0; ks < 4; ++ks) {
            uint32_t ahi[4][4], alo[4][4], bhi[4][2], blo[4][2];
            #pragma unroll
            for (int im = 0; im < 4; ++im) {
                uint32_t ao = aOff + (uint32_t)(im * 16 * SA_ + ks * 16) * 2;
                ldmatrix_x4(ahi[im][0], ahi[im][1], ahi[im][2], ahi[im][3],
                            base + OFF_AHI + ao);
                ldmatrix_x4(alo[im][0], alo[im][1], alo[im][2], alo[im][3],
                            base + OFF_ALO + ao);
            }
            #pragma unroll
            for (int in16 = 0; in16 < 2; ++in16) {
                uint32_t bo = bOff + (uint32_t)(in16 * 16 * SA_ + ks * 16) * 2;
                ldmatrix_x4(bhi[in16 * 2][0], bhi[in16 * 2][1],
                            bhi[in16 * 2 + 1][0], bhi[in16 * 2 + 1][1],
                            base + OFF_BHI + bo);
                ldmatrix_x4(blo[in16 * 2][0], blo[in16 * 2][1],
                            blo[in16 * 2 + 1][0], blo[in16 * 2 + 1][1],
                            base + OFF_BLO + bo);
            }
            #pragma unroll
            for (int im = 0; im < 4; ++im)
                #pragma unroll
                for (int j = 0; j < 4; ++j) {
                    mma16816(acc[im][j], ahi[im], bhi[j]);
                    mma16816(acc[im][j], ahi[im], blo[j]);
                    mma16816(acc[im][j], alo[im], bhi[j]);
                }
        }
        __syncthreads();   // all warps done before next stage overwrites
    }

    // Epilogue
    #pragma unroll
    for (int im = 0; im < 4; ++im) {
        int row = brow + warp_m * 64 + im * 16 + (l >> 2);
        #pragma unroll
        for (int j = 0; j < 4; ++j) {
            int col = bcol + warp_n * 32 + j * 8 + (l & 3) * 2;
            float2 v0 = {acc[im][j][0], acc[im][j][1]};
            float2 v1 = {acc[im][j][2], acc[im][j][3]};
            if (bias) {
                float2 bv = *reinterpret_cast<const float2*>(bias + col);
                v0.x += bv.x; v0.y += bv.y; v1.x += bv.x; v1.y += bv.y;
            }
            *reinterpret_cast<float2*>(C + (size_t)row * Ndim + col) = v0;
            *reinterpret_cast<float2*>(C + (size_t)(row + 8) * Ndim + col) = v1;
        }
    }
}

// ---------------------------------------------------------------------------
// Flash attention (fp32 SIMT) — emits hi/lo bf16 output
// ---------------------------------------------------------------------------
#define KB 32

__global__ __launch_bounds__(128) void attn_kernel(
    const float* __restrict__ Q, const float* __restrict__ K,
    const float* __restrict__ V,
    __nv_bfloat16* __restrict__ AOhi, __nv_bfloat16* __restrict__ AOlo)
{
    __shared__ float Ks[KB][D_];
    __shared__ float Vs[KB][D_];
    __shared__ float Ssm[KB][128];

    const int t = threadIdx.x;
    const int b = blockIdx.z;
    const int h = blockIdx.y;
    const int n = blockIdx.x * 128 + t;
    const float scale = 0.125f;

    const float* qp = Q + ((size_t)(b * N_ + n) * INNER) + h * D_;
    float q[D_];
    #pragma unroll
    for (int d = 0; d < D_; d += 4) {
        float4 v = *reinterpret_cast<const float4*>(qp + d);
        q[d] = v.x * scale; q[d + 1] = v.y * scale;
        q[d + 2] = v.z * scale; q[d + 3] = v.w * scale;
    }

    float o[D_];
    #pragma unroll
    for (int d = 0; d < D_; ++d) o[d] = 0.f;
    float mrun = -1e30f, lrun = 0.f;

    for (int kb = 0; kb < M_; kb += KB) {
        __syncthreads();
        #pragma unroll
        for (int i = 0; i < (KB * D_) / (128 * 4); ++i) {
            int idx = t + i * 128;
            int j = idx >> 4;
            int dv = (idx & 15) * 4;
            size_t g = ((size_t)(b * M_ + kb + j) * INNER) + h * D_ + dv;
            *reinterpret_cast<float4*>(&Ks[j][dv]) = *reinterpret_cast<const float4*>(K + g);
            *reinterpret_cast<float4*>(&Vs[j][dv]) = *reinterpret_cast<const float4*>(V + g);
        }
        __syncthreads();

        float bm = -1e30f;
        #pragma unroll 8
        for (int j = 0; j < KB; ++j) {
            float acc = 0.f;
            #pragma unroll
            for (int d = 0; d < D_; d += 4) {
                float4 kv = *reinterpret_cast<const float4*>(&Ks[j][d]);
                acc += q[d] * kv.x + q[d + 1] * kv.y + q[d + 2] * kv.z + q[d + 3] * kv.w;
            }
            Ssm[j][t] = acc;
            bm = fmaxf(bm, acc);
        }

        float mnew  = fmaxf(mrun, bm);
        float alpha = __expf(mrun - mnew);
        lrun *= alpha;
        #pragma unroll
        for (int d = 0; d < D_; ++d) o[d] *= alpha;
        mrun = mnew;

        #pragma unroll 4
        for (int j = 0; j < KB; ++j) {
            float p = __expf(Ssm[j][t] - mnew);
            lrun += p;
            #pragma unroll
            for (int d = 0; d < D_; d += 4) {
                float4 vv = *reinterpret_cast<const float4*>(&Vs[j][d]);
                o[d]     += p * vv.x; o[d + 1] += p * vv.y;
                o[d + 2] += p * vv.z; o[d + 3] += p * vv.w;
            }
        }
    }

    float inv = 1.f / lrun;
    size_t base = ((size_t)(b * N_ + n) * INNER) + h * D_;
    #pragma unroll
    for (int d = 0; d < D_; d += 2) {
        float v0 = o[d] * inv, v1 = o[d + 1] * inv;
        __nv_bfloat16 h0 = __float2bfloat16(v0), h1 = __float2bfloat16(v1);
        __nv_bfloat16 l0 = __float2bfloat16(v0 - __bfloat162float(h0));
        __nv_bfloat16 l1 = __float2bfloat16(v1 - __bfloat162float(h1));
        *reinterpret_cast<__nv_bfloat162*>(AOhi + base + d) = __halves2bfloat162(h0, h1);
        *reinterpret_cast<__nv_bfloat162*>(AOlo + base + d) = __halves2bfloat162(l0, l1);
    }
}

// ---------------------------------------------------------------------------
// Launch
// ---------------------------------------------------------------------------
extern "C" void kernel_launch(void* const* d_in, const int* in_sizes, int n_in,
                              void* d_out, int out_size)
{
    const float* x   = (const float*)d_in[0];
    const float* ctx = (const float*)d_in[1];
    const float* Wq  = (const float*)d_in[2];
    const float* Wk  = (const float*)d_in[3];
    const float* Wv  = (const float*)d_in[4];
    const float* Wo  = (const float*)d_in[5];
    const float* bo  = (const float*)d_in[6];
    float* out = (float*)d_out;

    cudaFuncSetAttribute(mma_gemm_kernel,
                         cudaFuncAttributeMaxDynamicSharedMemorySize, GEMM_SMEM);

    float *Qb, *Kb, *Vb;
    __nv_bfloat16 *xhi, *xlo, *chi, *clo, *aohi, *aolo;
    __nv_bfloat16 *wqh, *wql, *wkh, *wkl, *wvh, *wvl, *woh, *wol;
    cudaGetSymbolAddress((void**)&Qb,  g_Q);
    cudaGetSymbolAddress((void**)&Kb,  g_K);
    cudaGetSymbolAddress((void**)&Vb,  g_V);
    cudaGetSymbolAddress((void**)&xhi, g_xhi);  cudaGetSymbolAddress((void**)&xlo, g_xlo);
    cudaGetSymbolAddress((void**)&chi, g_chi);  cudaGetSymbolAddress((void**)&clo, g_clo);
    cudaGetSymbolAddress((void**)&aohi, g_AOhi); cudaGetSymbolAddress((void**)&aolo, g_AOlo);
    cudaGetSymbolAddress((void**)&wqh, g_WqThi); cudaGetSymbolAddress((void**)&wql, g_WqTlo);
    cudaGetSymbolAddress((void**)&wkh, g_WkThi); cudaGetSymbolAddress((void**)&wkl, g_WkTlo);
    cudaGetSymbolAddress((void**)&wvh, g_WvThi); cudaGetSymbolAddress((void**)&wvl, g_WvTlo);
    cudaGetSymbolAddress((void**)&woh, g_WoThi); cudaGetSymbolAddress((void**)&wol, g_WoTlo);

    // 1. Split-convert activations
    {
        int n4 = (BNQ * QD_) / 4;
        cvt_hilo_kernel<<<n4 / 256, 256>>>(x, xhi, xlo, n4);
        n4 = (BMC * CD_) / 4;
        cvt_hilo_kernel<<<n4 / 256, 256>>>(ctx, chi, clo, n4);
    }
    // 2. Transpose-convert weights: W[K,N] -> WT[N,K] hi/lo
    transpose_cvt_kernel<<<dim3(INNER / 32, QD_ / 32), dim3(32, 8)>>>(Wq, wqh, wql, QD_, INNER);
    transpose_cvt_kernel<<<dim3(INNER / 32, CD_ / 32), dim3(32, 8)>>>(Wk, wkh, wkl, CD_, INNER);
    transpose_cvt_kernel<<<dim3(INNER / 32, CD_ / 32), dim3(32, 8)>>>(Wv, wvh, wvl, CD_, INNER);
    transpose_cvt_kernel<<<dim3(QD_ / 32, INNER / 32), dim3(32, 8)>>>(Wo, woh, wol, INNER, QD_);

    // 3. Projections (mma.sync tensor cores)
    mma_gemm_kernel<<<dim3(INNER / 128, BNQ / 128), 256, GEMM_SMEM>>>(
        xhi, xlo, wqh, wql, Qb, INNER, QD_, nullptr);
    mma_gemm_kernel<<<dim3(INNER / 128, BMC / 128), 256, GEMM_SMEM>>>(
        chi, clo, wkh, wkl, Kb, INNER, CD_, nullptr);
    mma_gemm_kernel<<<dim3(INNER / 128, BMC / 128), 256, GEMM_SMEM>>>(
        chi, clo, wvh, wvl, Vb, INNER, CD_, nullptr);

    // 4. Attention (fp32 SIMT), emits hi/lo bf16
    attn_kernel<<<dim3(N_ / 128, H_, B_), 128>>>(Qb, Kb, Vb, aohi, aolo);

    // 5. Output projection + bias -> d_out
    mma_gemm_kernel<<<dim3(QD_ / 128, BNQ / 128), 256, GEMM_SMEM>>>(
        aohi, aolo, woh, wol, out, QD_, INNER, bo);
}

// round 5
// speedup vs baseline: 3.0071x; 2.2758x over previous
#include <cuda_runtime.h>
#include <cuda_bf16.h>
#include <cstdint>
#include <cstddef>

// Problem constants
#define B_    4
#define N_    4096
#define M_    1024
#define QD_   1024
#define CD_   768
#define H_    16
#define D_    64
#define INNER 1024
#define BNQ   (B_ * N_)   // 16384 query rows
#define BMC   (B_ * M_)   // 4096 context rows

// ---------------------------------------------------------------------------
// Static device scratch
// ---------------------------------------------------------------------------
__device__ __nv_bfloat16 g_Qhi[BNQ * INNER], g_Qlo[BNQ * INNER];
__device__ __nv_bfloat16 g_Khi[BMC * INNER], g_Klo[BMC * INNER];
__device__ __nv_bfloat16 g_Vhi[BMC * INNER], g_Vlo[BMC * INNER];

__device__ __nv_bfloat16 g_xhi[BNQ * QD_],  g_xlo[BNQ * QD_];
__device__ __nv_bfloat16 g_chi[BMC * CD_],  g_clo[BMC * CD_];
__device__ __nv_bfloat16 g_WqThi[INNER * QD_], g_WqTlo[INNER * QD_];
__device__ __nv_bfloat16 g_WkThi[INNER * CD_], g_WkTlo[INNER * CD_];
__device__ __nv_bfloat16 g_WvThi[INNER * CD_], g_WvTlo[INNER * CD_];
__device__ __nv_bfloat16 g_WoThi[QD_ * INNER], g_WoTlo[QD_ * INNER];
__device__ __nv_bfloat16 g_AOhi[BNQ * INNER], g_AOlo[BNQ * INNER];

// ---------------------------------------------------------------------------
// PTX helpers (base sm_80/90 features only)
// ---------------------------------------------------------------------------
__device__ __forceinline__ uint32_t smem_u32(const void* p) {
    uint32_t a;
    asm("{ .reg .u64 t; cvta.to.shared.u64 t, %1; cvt.u32.u64 %0, t; }"
        : "=r"(a) : "l"(p));
    return a;
}

__device__ __forceinline__ void cp_async16(uint32_t dst, const void* src) {
    asm volatile("cp.async.cg.shared.global [%0], [%1], 16;"
                 :: "r"(dst), "l"(src) : "memory");
}
#define CP_COMMIT() asm volatile("cp.async.commit_group;" ::: "memory")
#define CP_WAIT(n)  asm volatile("cp.async.wait_group %0;" :: "n"(n) : "memory")

__device__ __forceinline__ void ldmatrix_x4(uint32_t& r0, uint32_t& r1,
                                            uint32_t& r2, uint32_t& r3, uint32_t a) {
    asm volatile("ldmatrix.sync.aligned.m8n8.x4.shared.b16 {%0,%1,%2,%3}, [%4];"
                 : "=r"(r0), "=r"(r1), "=r"(r2), "=r"(r3) : "r"(a));
}

__device__ __forceinline__ void ldmatrix_x4_t(uint32_t& r0, uint32_t& r1,
                                              uint32_t& r2, uint32_t& r3, uint32_t a) {
    asm volatile("ldmatrix.sync.aligned.m8n8.x4.trans.shared.b16 {%0,%1,%2,%3}, [%4];"
                 : "=r"(r0), "=r"(r1), "=r"(r2), "=r"(r3) : "r"(a));
}

__device__ __forceinline__ void mma16816(float* d, const uint32_t* a,
                                         const uint32_t* b) {
    asm volatile(
        "mma.sync.aligned.m16n8k16.row.col.f32.bf16.bf16.f32 "
        "{%0,%1,%2,%3}, {%4,%5,%6,%7}, {%8,%9}, {%0,%1,%2,%3};"
        : "+f"(d[0]), "+f"(d[1]), "+f"(d[2]), "+f"(d[3])
        : "r"(a[0]), "r"(a[1]), "r"(a[2]), "r"(a[3]), "r"(b[0]), "r"(b[1]));
}

// Truncation hi/lo split, packed as bf16x2 (element0 = low half = v0)
__device__ __forceinline__ uint32_t pack_hi2(float v0, float v1) {
    return __byte_perm(__float_as_uint(v0), __float_as_uint(v1), 0x7632);
}
__device__ __forceinline__ uint32_t pack_lo2(float v0, float v1) {
    float l0 = v0 - __uint_as_float(__float_as_uint(v0) & 0xffff0000u);
    float l1 = v1 - __uint_as_float(__float_as_uint(v1) & 0xffff0000u);
    uint32_t r;
    asm("cvt.rn.bf16x2.f32 %0, %1, %2;" : "=r"(r) : "f"(l1), "f"(l0));
    return r;
}

// ---------------------------------------------------------------------------
// Conversion kernels: fp32 -> (hi, lo) bf16 split
// ---------------------------------------------------------------------------
__global__ void cvt_hilo_kernel(const float* __restrict__ in,
                                __nv_bfloat16* __restrict__ hi,
                                __nv_bfloat16* __restrict__ lo, int n4)
{
    int i = blockIdx.x * blockDim.x + threadIdx.x;
    if (i >= n4) return;
    float4 v = reinterpret_cast<const float4*>(in)[i];
    reinterpret_cast<uint32_t*>(hi)[i * 2 + 0] = pack_hi2(v.x, v.y);
    reinterpret_cast<uint32_t*>(hi)[i * 2 + 1] = pack_hi2(v.z, v.w);
    reinterpret_cast<uint32_t*>(lo)[i * 2 + 0] = pack_lo2(v.x, v.y);
    reinterpret_cast<uint32_t*>(lo)[i * 2 + 1] = pack_lo2(v.z, v.w);
}

// W [K,N] row-major  ->  T [N,K] (hi, lo) bf16
__global__ void transpose_cvt_kernel(const float* __restrict__ W,
                                     __nv_bfloat16* __restrict__ Thi,
                                     __nv_bfloat16* __restrict__ Tlo, int K, int N)
{
    __shared__ float t[32][33];
    int tx = threadIdx.x, ty = threadIdx.y;          // 32 x 8
    int n0 = blockIdx.x * 32, k0 = blockIdx.y * 32;
    #pragma unroll
    for (int j = 0; j < 4; ++j)
        t[ty + j * 8][tx] = W[(size_t)(k0 + ty + j * 8) * N + n0 + tx];
    __syncthreads();
    #pragma unroll
    for (int j = 0; j < 4; ++j) {
        float v = t[tx][ty + j * 8];
        int n = n0 + ty + j * 8, k = k0 + tx;
        uint32_t u = __float_as_uint(v);
        float hv = __uint_as_float(u & 0xffff0000u);
        Thi[(size_t)n * K + k] = __ushort_as_bfloat16((unsigned short)(u >> 16));
        Tlo[(size_t)n * K + k] = __float2bfloat16(v - hv);
    }
}

// ---------------------------------------------------------------------------
// mma.sync GEMM: C = A @ B^T (B stored [N,K] K-major), split-bf16 x3.
// BF16OUT: write (hi, lo) bf16 with scale folded; else fp32 (+bias).
// ---------------------------------------------------------------------------
#define SA_        72
#define TILE_B     (128 * SA_ * 2)
#define OFF_AHI    0
#define OFF_ALO    (TILE_B)
#define OFF_BHI    (2 * TILE_B)
#define OFF_BLO    (3 * TILE_B)
#define BUF_B      (4 * TILE_B)
#define GEMM_SMEM  (2 * BUF_B)

template <bool BF16OUT>
__global__ __launch_bounds__(256) void mma_gemm_kernel(
    const __nv_bfloat16* __restrict__ Ahi, const __nv_bfloat16* __restrict__ Alo,
    const __nv_bfloat16* __restrict__ Bhi, const __nv_bfloat16* __restrict__ Blo,
    float* __restrict__ C, __nv_bfloat16* __restrict__ Chi,
    __nv_bfloat16* __restrict__ Clo, float scale,
    int Ndim, int Kdim, const float* __restrict__ bias)
{
    extern __shared__ __align__(128) char smem[];
    const uint32_t sb = smem_u32(smem);
    const int tid = threadIdx.x, wid = tid >> 5, l = tid & 31;
    const int warp_m = wid >> 2, warp_n = wid & 3;
    const int brow = blockIdx.y * 128, bcol = blockIdx.x * 128;

    const int a_row = warp_m * 64 + (l & 7) + ((l >> 3) & 1) * 8;
    const int a_col = ((l >> 4) & 1) * 8;
    const int b_row = warp_n * 32 + (l & 7) + ((l >> 4) & 1) * 8;
    const int b_col = ((l >> 3) & 1) * 8;
    const uint32_t aOff = (uint32_t)(a_row * SA_ + a_col) * 2;
    const uint32_t bOff = (uint32_t)(b_row * SA_ + b_col) * 2;

    float acc[4][4][4];
    #pragma unroll
    for (int im = 0; im < 4; ++im)
        #pragma unroll
        for (int j = 0; j < 4; ++j)
            #pragma unroll
            for (int q = 0; q < 4; ++q) acc[im][j][q] = 0.f;

    const int nch = Kdim >> 6;

    auto stage = [&](int ch, int bb) {
        const int k0 = ch << 6;
        const uint32_t base = sb + bb * BUF_B;
        #pragma unroll
        for (int i = 0; i < 4; ++i) {
            int s = tid + i * 256;
            int r = s >> 3, c = s & 7;
            uint32_t so = (uint32_t)(r * 144 + c * 16);
            size_t ga = (size_t)(brow + r) * Kdim + k0 + c * 8;
            size_t gb = (size_t)(bcol + r) * Kdim + k0 + c * 8;
            cp_async16(base + OFF_AHI + so, Ahi + ga);
            cp_async16(base + OFF_ALO + so, Alo + ga);
            cp_async16(base + OFF_BHI + so, Bhi + gb);
            cp_async16(base + OFF_BLO + so, Blo + gb);
        }
        CP_COMMIT();
    };

    stage(0, 0);

    for (int ch = 0; ch < nch; ++ch) {
        const int bb = ch & 1;
        if (ch + 1 < nch) { stage(ch + 1, bb ^ 1); CP_WAIT(1); }
        else              { CP_WAIT(0); }
        __syncthreads();

        const uint32_t base = sb + bb * BUF_B;
        #pragma unroll
        for (int ks = 0; ks < 4; ++ks) {
            uint32_t ahi[4][4], alo[4][4], bhi[4][2], blo[4][2];
            #pragma unroll
            for (int im = 0; im < 4; ++im) {
                uint32_t ao = aOff + (uint32_t)(im * 16 * SA_ + ks * 16) * 2;
                ldmatrix_x4(ahi[im][0], ahi[im][1], ahi[im][2], ahi[im][3],
                            base + OFF_AHI + ao);
                ldmatrix_x4(alo[im][0], alo[im][1], alo[im][2], alo[im][3],
                            base + OFF_ALO + ao);
            }
            #pragma unroll
            for (int in16 = 0; in16 < 2; ++in16) {
                uint32_t bo = bOff + (uint32_t)(in16 * 16 * SA_ + ks * 16) * 2;
                ldmatrix_x4(bhi[in16 * 2][0], bhi[in16 * 2][1],
                            bhi[in16 * 2 + 1][0], bhi[in16 * 2 + 1][1],
                            base + OFF_BHI + bo);
                ldmatrix_x4(blo[in16 * 2][0], blo[in16 * 2][1],
                            blo[in16 * 2 + 1][0], blo[in16 * 2 + 1][1],
                            base + OFF_BLO + bo);
            }
            #pragma unroll
            for (int im = 0; im < 4; ++im)
                #pragma unroll
                for (int j = 0; j < 4; ++j) {
                    mma16816(acc[im][j], ahi[im], bhi[j]);
                    mma16816(acc[im][j], ahi[im], blo[j]);
                    mma16816(acc[im][j], alo[im], bhi[j]);
                }
        }
        __syncthreads();
    }

    #pragma unroll
    for (int im = 0; im < 4; ++im) {
        int row = brow + warp_m * 64 + im * 16 + (l >> 2);
        #pragma unroll
        for (int j = 0; j < 4; ++j) {
            int col = bcol + warp_n * 32 + j * 8 + (l & 3) * 2;
            if (BF16OUT) {
                float v0 = acc[im][j][0] * scale, v1 = acc[im][j][1] * scale;
                float v2 = acc[im][j][2] * scale, v3 = acc[im][j][3] * scale;
                size_t o0 = (size_t)row * Ndim + col;
                size_t o1 = (size_t)(row + 8) * Ndim + col;
                *reinterpret_cast<uint32_t*>(Chi + o0) = pack_hi2(v0, v1);
                *reinterpret_cast<uint32_t*>(Clo + o0) = pack_lo2(v0, v1);
                *reinterpret_cast<uint32_t*>(Chi + o1) = pack_hi2(v2, v3);
                *reinterpret_cast<uint32_t*>(Clo + o1) = pack_lo2(v2, v3);
            } else {
                float2 v0 = {acc[im][j][0], acc[im][j][1]};
                float2 v1 = {acc[im][j][2], acc[im][j][3]};
                if (bias) {
                    float2 bv = *reinterpret_cast<const float2*>(bias + col);
                    v0.x += bv.x; v0.y += bv.y; v1.x += bv.x; v1.y += bv.y;
                }
                *reinterpret_cast<float2*>(C + (size_t)row * Ndim + col) = v0;
                *reinterpret_cast<float2*>(C + (size_t)(row + 8) * Ndim + col) = v1;
            }
        }
    }
}

// ---------------------------------------------------------------------------
// FA2-style attention, mma.sync, split-bf16 x3 on both matmuls.
// CTA = (b, h, 128 q rows); 8 warps x 16 rows; kv tile = 64, double-buffered.
// smem per stage: Khi | Klo | Vhi | Vlo, each 64 x 72 bf16 (9216 B).
// ---------------------------------------------------------------------------
#define AT_STG    36864
#define AT_SMEM   (2 * AT_STG)
#define AT_KLO    9216
#define AT_VHI    18432
#define AT_VLO    27648

__global__ __launch_bounds__(256) void attn_mma_kernel(
    const __nv_bfloat16* __restrict__ Qhi, const __nv_bfloat16* __restrict__ Qlo,
    const __nv_bfloat16* __restrict__ Khi, const __nv_bfloat16* __restrict__ Klo,
    const __nv_bfloat16* __restrict__ Vhi, const __nv_bfloat16* __restrict__ Vlo,
    __nv_bfloat16* __restrict__ AOhi, __nv_bfloat16* __restrict__ AOlo)
{
    extern __shared__ __align__(128) char smem[];
    const uint32_t sb = smem_u32(smem);
    const int tid = threadIdx.x, wid = tid >> 5, l = tid & 31;
    const int b = blockIdx.z, h = blockIdx.y;
    const int q0 = blockIdx.x * 128;
    const size_t qrow0 = (size_t)(b * N_ + q0);
    const size_t krow0 = (size_t)(b * M_);
    const int hc = h * 64;

    // ---- Stage Q tile (128 x 64 hi/lo) into stage-0 region, build A frags
    #pragma unroll
    for (int i = 0; i < 4; ++i) {
        int s = tid + i * 256;               // 0..1023
        int r = s >> 3, c = s & 7;
        uint32_t so = (uint32_t)(r * 144 + c * 16);
        size_t g = (qrow0 + r) * INNER + hc + c * 8;
        cp_async16(sb + so, Qhi + g);
        cp_async16(sb + 18432 + so, Qlo + g);
    }
    CP_COMMIT(); CP_WAIT(0);
    __syncthreads();

    uint32_t qh[4][4], ql[4][4];
    {
        int ar = wid * 16 + (l & 7) + ((l >> 3) & 1) * 8;
        int ac = ((l >> 4) & 1) * 8;
        #pragma unroll
        for (int ks = 0; ks < 4; ++ks) {
            uint32_t ad = sb + (uint32_t)(ar * SA_ + ac + ks * 16) * 2;
            ldmatrix_x4(qh[ks][0], qh[ks][1], qh[ks][2], qh[ks][3], ad);
            ldmatrix_x4(ql[ks][0], ql[ks][1], ql[ks][2], ql[ks][3], ad + 18432);
        }
    }
    __syncthreads();

    float o[8][4];
    #pragma unroll
    for (int j = 0; j < 8; ++j)
        #pragma unroll
        for (int q = 0; q < 4; ++q) o[j][q] = 0.f;
    float m0 = -1e30f, m1 = -1e30f, lp0 = 0.f, lp1 = 0.f;

    auto stageKV = [&](int t, int bb) {
        const uint32_t base = sb + bb * AT_STG;
        const int kv0 = t * 64;
        #pragma unroll
        for (int i = 0; i < 2; ++i) {
            int s = tid + i * 256;           // 0..511
            int r = s >> 3, c = s & 7;
            uint32_t so = (uint32_t)(r * 144 + c * 16);
            size_t g = (krow0 + kv0 + r) * INNER + hc + c * 8;
            cp_async16(base + so,          Khi + g);
            cp_async16(base + AT_KLO + so, Klo + g);
            cp_async16(base + AT_VHI + so, Vhi + g);
            cp_async16(base + AT_VLO + so, Vlo + g);
        }
        CP_COMMIT();
    };

    stageKV(0, 0);

    const int nr  = (l & 7) + ((l >> 4) & 1) * 8;    // K-frag row in tile
    const int kc8 = ((l >> 3) & 1) * 8;              // K-frag col offset
    const int vg  = l >> 3, vi = l & 7;              // V trans-frag coords

    for (int t = 0; t < M_ / 64; ++t) {
        const int bb = t & 1;
        if (t + 1 < M_ / 64) { stageKV(t + 1, bb ^ 1); CP_WAIT(1); }
        else                 { CP_WAIT(0); }
        __syncthreads();
        const uint32_t kb = sb + bb * AT_STG;

        // ---- S = Q K^T (3 split products)
        float s[8][4];
        #pragma unroll
        for (int j = 0; j < 8; ++j)
            #pragma unroll
            for (int q = 0; q < 4; ++q) s[j][q] = 0.f;

        #pragma unroll
        for (int ks = 0; ks < 4; ++ks) {
            #pragma unroll
            for (int jn = 0; jn < 4; ++jn) {
                uint32_t ad = kb + (uint32_t)((jn * 16 + nr) * SA_ + ks * 16 + kc8) * 2;
                uint32_t h0, h1, h2, h3, l0, l1, l2, l3;
                ldmatrix_x4(h0, h1, h2, h3, ad);
                ldmatrix_x4(l0, l1, l2, l3, ad + AT_KLO);
                uint32_t bh0[2] = {h0, h1}, bh1[2] = {h2, h3};
                uint32_t bl0[2] = {l0, l1}, bl1[2] = {l2, l3};
                mma16816(s[2 * jn],     qh[ks], bh0);
                mma16816(s[2 * jn],     qh[ks], bl0);
                mma16816(s[2 * jn],     ql[ks], bh0);
                mma16816(s[2 * jn + 1], qh[ks], bh1);
                mma16816(s[2 * jn + 1], qh[ks], bl1);
                mma16816(s[2 * jn + 1], ql[ks], bh1);
            }
        }

        // ---- online softmax (rows r = l/4 and r+8)
        float mx0 = -1e30f, mx1 = -1e30f;
        #pragma unroll
        for (int j = 0; j < 8; ++j) {
            mx0 = fmaxf(mx0, fmaxf(s[j][0], s[j][1]));
            mx1 = fmaxf(mx1, fmaxf(s[j][2], s[j][3]));
        }
        mx0 = fmaxf(mx0, __shfl_xor_sync(0xffffffffu, mx0, 1));
        mx0 = fmaxf(mx0, __shfl_xor_sync(0xffffffffu, mx0, 2));
        mx1 = fmaxf(mx1, __shfl_xor_sync(0xffffffffu, mx1, 1));
        mx1 = fmaxf(mx1, __shfl_xor_sync(0xffffffffu, mx1, 2));

        float nm0 = fmaxf(m0, mx0), nm1 = fmaxf(m1, mx1);
        float al0 = __expf(m0 - nm0), al1 = __expf(m1 - nm1);
        m0 = nm0; m1 = nm1;

        float add0 = 0.f, add1 = 0.f;
        #pragma unroll
        for (int j = 0; j < 8; ++j) {
            s[j][0] = __expf(s[j][0] - nm0);
            s[j][1] = __expf(s[j][1] - nm0);
            s[j][2] = __expf(s[j][2] - nm1);
            s[j][3] = __expf(s[j][3] - nm1);
            add0 += s[j][0] + s[j][1];
            add1 += s[j][2] + s[j][3];
        }
        lp0 = lp0 * al0 + add0;
        lp1 = lp1 * al1 + add1;
        #pragma unroll
        for (int j = 0; j < 8; ++j) {
            o[j][0] *= al0; o[j][1] *= al0;
            o[j][2] *= al1; o[j][3] *= al1;
        }

        // ---- AV (3 split products), P frags built from s in-registers
        #pragma unroll
        for (int t2 = 0; t2 < 4; ++t2) {
            uint32_t pah[4], pal[4];
            pah[0] = pack_hi2(s[2 * t2][0],     s[2 * t2][1]);
            pah[1] = pack_hi2(s[2 * t2][2],     s[2 * t2][3]);
            pah[2] = pack_hi2(s[2 * t2 + 1][0], s[2 * t2 + 1][1]);
            pah[3] = pack_hi2(s[2 * t2 + 1][2], s[2 * t2 + 1][3]);
            pal[0] = pack_lo2(s[2 * t2][0],     s[2 * t2][1]);
            pal[1] = pack_lo2(s[2 * t2][2],     s[2 * t2][3]);
            pal[2] = pack_lo2(s[2 * t2 + 1][0], s[2 * t2 + 1][1]);
            pal[3] = pack_lo2(s[2 * t2 + 1][2], s[2 * t2 + 1][3]);

            #pragma unroll
            for (int jn = 0; jn < 4; ++jn) {
                uint32_t ad = kb + AT_VHI +
                    (uint32_t)((t2 * 16 + (vg & 1) * 8 + vi) * SA_ +
                               jn * 16 + (vg >> 1) * 8) * 2;
                uint32_t h0, h1, h2, h3, l0, l1, l2, l3;
                ldmatrix_x4_t(h0, h1, h2, h3, ad);
                ldmatrix_x4_t(l0, l1, l2, l3, ad + (AT_VLO - AT_VHI));
                uint32_t bh0[2] = {h0, h1}, bh1[2] = {h2, h3};
                uint32_t bl0[2] = {l0, l1}, bl1[2] = {l2, l3};
                mma16816(o[2 * jn],     pah, bh0);
                mma16816(o[2 * jn],     pah, bl0);
                mma16816(o[2 * jn],     pal, bh0);
                mma16816(o[2 * jn + 1], pah, bh1);
                mma16816(o[2 * jn + 1], pah, bl1);
                mma16816(o[2 * jn + 1], pal, bh1);
            }
        }
        __syncthreads();
    }

    // ---- normalize + write hi/lo bf16
    lp0 += __shfl_xor_sync(0xffffffffu, lp0, 1);
    lp0 += __shfl_xor_sync(0xffffffffu, lp0, 2);
    lp1 += __shfl_xor_sync(0xffffffffu, lp1, 1);
    lp1 += __shfl_xor_sync(0xffffffffu, lp1, 2);
    float inv0 = 1.f / lp0, inv1 = 1.f / lp1;

    size_t r0g = (qrow0 + wid * 16 + (l >> 2)) * INNER + hc;
    size_t r1g = r0g + (size_t)8 * INNER;
    #pragma unroll
    for (int j = 0; j < 8; ++j) {
        int c = j * 8 + (l & 3) * 2;
        float v0 = o[j][0] * inv0, v1 = o[j][1] * inv0;
        float v2 = o[j][2] * inv1, v3 = o[j][3] * inv1;
        *reinterpret_cast<uint32_t*>(AOhi + r0g + c) = pack_hi2(v0, v1);
        *reinterpret_cast<uint32_t*>(AOlo + r0g + c) = pack_lo2(v0, v1);
        *reinterpret_cast<uint32_t*>(AOhi + r1g + c) = pack_hi2(v2, v3);
        *reinterpret_cast<uint32_t*>(AOlo + r1g + c) = pack_lo2(v2, v3);
    }
}

// ---------------------------------------------------------------------------
// Launch
// ---------------------------------------------------------------------------
extern "C" void kernel_launch(void* const* d_in, const int* in_sizes, int n_in,
                              void* d_out, int out_size)
{
    const float* x   = (const float*)d_in[0];
    const float* ctx = (const float*)d_in[1];
    const float* Wq  = (const float*)d_in[2];
    const float* Wk  = (const float*)d_in[3];
    const float* Wv  = (const float*)d_in[4];
    const float* Wo  = (const float*)d_in[5];
    const float* bo  = (const float*)d_in[6];
    float* out = (float*)d_out;

    cudaFuncSetAttribute(mma_gemm_kernel<true>,
                         cudaFuncAttributeMaxDynamicSharedMemorySize, GEMM_SMEM);
    cudaFuncSetAttribute(mma_gemm_kernel<false>,
                         cudaFuncAttributeMaxDynamicSharedMemorySize, GEMM_SMEM);
    cudaFuncSetAttribute(attn_mma_kernel,
                         cudaFuncAttributeMaxDynamicSharedMemorySize, AT_SMEM);

    __nv_bfloat16 *qhi, *qlo, *khi, *klo, *vhi, *vlo;
    __nv_bfloat16 *xhi, *xlo, *chi, *clo, *aohi, *aolo;
    __nv_bfloat16 *wqh, *wql, *wkh, *wkl, *wvh, *wvl, *woh, *wol;
    cudaGetSymbolAddress((void**)&qhi, g_Qhi);  cudaGetSymbolAddress((void**)&qlo, g_Qlo);
    cudaGetSymbolAddress((void**)&khi, g_Khi);  cudaGetSymbolAddress((void**)&klo, g_Klo);
    cudaGetSymbolAddress((void**)&vhi, g_Vhi);  cudaGetSymbolAddress((void**)&vlo, g_Vlo);
    cudaGetSymbolAddress((void**)&xhi, g_xhi);  cudaGetSymbolAddress((void**)&xlo, g_xlo);
    cudaGetSymbolAddress((void**)&chi, g_chi);  cudaGetSymbolAddress((void**)&clo, g_clo);
    cudaGetSymbolAddress((void**)&aohi, g_AOhi); cudaGetSymbolAddress((void**)&aolo, g_AOlo);
    cudaGetSymbolAddress((void**)&wqh, g_WqThi); cudaGetSymbolAddress((void**)&wql, g_WqTlo);
    cudaGetSymbolAddress((void**)&wkh, g_WkThi); cudaGetSymbolAddress((void**)&wkl, g_WkTlo);
    cudaGetSymbolAddress((void**)&wvh, g_WvThi); cudaGetSymbolAddress((void**)&wvl, g_WvTlo);
    cudaGetSymbolAddress((void**)&woh, g_WoThi); cudaGetSymbolAddress((void**)&wol, g_WoTlo);

    // 1. Split-convert inputs
    {
        int n4 = (BNQ * QD_) / 4;
        cvt_hilo_kernel<<<n4 / 256, 256>>>(x, xhi, xlo, n4);
        n4 = (BMC * CD_) / 4;
        cvt_hilo_kernel<<<n4 / 256, 256>>>(ctx, chi, clo, n4);
    }
    transpose_cvt_kernel<<<dim3(INNER / 32, QD_ / 32), dim3(32, 8)>>>(Wq, wqh, wql, QD_, INNER);
    transpose_cvt_kernel<<<dim3(INNER / 32, CD_ / 32), dim3(32, 8)>>>(Wk, wkh, wkl, CD_, INNER);
    transpose_cvt_kernel<<<dim3(INNER / 32, CD_ / 32), dim3(32, 8)>>>(Wv, wvh, wvl, CD_, INNER);
    transpose_cvt_kernel<<<dim3(QD_ / 32, INNER / 32), dim3(32, 8)>>>(Wo, woh, wol, INNER, QD_);

    // 2. Projections -> hi/lo bf16 (Q with softmax scale folded in)
    mma_gemm_kernel<true><<<dim3(INNER / 128, BNQ / 128), 256, GEMM_SMEM>>>(
        xhi, xlo, wqh, wql, nullptr, qhi, qlo, 0.125f, INNER, QD_, nullptr);
    mma_gemm_kernel<true><<<dim3(INNER / 128, BMC / 128), 256, GEMM_SMEM>>>(
        chi, clo, wkh, wkl, nullptr, khi, klo, 1.0f, INNER, CD_, nullptr);
    mma_gemm_kernel<true><<<dim3(INNER / 128, BMC / 128), 256, GEMM_SMEM>>>(
        chi, clo, wvh, wvl, nullptr, vhi, vlo, 1.0f, INNER, CD_, nullptr);

    // 3. Attention (tensor-core FA2)
    attn_mma_kernel<<<dim3(N_ / 128, H_, B_), 256, AT_SMEM>>>(
        qhi, qlo, khi, klo, vhi, vlo, aohi, aolo);

    // 4. Output projection + bias -> d_out (fp32)
    mma_gemm_kernel<false><<<dim3(QD_ / 128, BNQ / 128), 256, GEMM_SMEM>>>(
        aohi, aolo, woh, wol, out, nullptr, nullptr, 1.0f, QD_, INNER, bo);
}